// round 16
// baseline (speedup 1.0000x reference)
#include <cuda_runtime.h>
#include <cuda_fp16.h>
#include <math.h>
#include <stdint.h>

// Problem constants (fixed shapes)
constexpr int Bb  = 2;
constexpr int Lc  = 4096;
constexpr int Dc  = 2048;
constexpr int Hh  = 32;
constexpr int Kc  = 16;
constexpr int HDc = 64;
constexpr int NMBc = 256;           // L / K
constexpr int Mrows = Bb * Lc;      // 8192

// Scratch (device globals; allocation in kernel_launch is forbidden)
__device__ float g_q  [(size_t)Bb*Hh*NMBc*Kc*HDc];   // scan layout [b][h][n][k][d]
__device__ float g_k  [(size_t)Bb*Hh*NMBc*Kc*HDc];
__device__ float g_v  [(size_t)Bb*Hh*NMBc*Kc*HDc];
__device__ float g_eta[(size_t)Bb*Hh*NMBc*Kc];
__device__ float g_attn[(size_t)Bb*Hh*NMBc*Kc*Kc];  // pre-masked (attn+1), tril
__device__ float g_y  [(size_t)Bb*Lc*Dc];            // scan output, token layout

// fp16 operands for tensor-core GEMMs (single-pass fp16)
__device__ __half g_ah [(size_t)Mrows*Dc];
__device__ __half g_wqh[(size_t)Dc*Dc];
__device__ __half g_wkh[(size_t)Dc*Dc];
__device__ __half g_wvh[(size_t)Dc*Dc];
__device__ __half g_woh[(size_t)Dc*Dc];
__device__ __half g_lrwt[(size_t)Dc*Dc];   // lr_w transposed [K][h], 128 cols used, stride Dc
__device__ __half g_xnh[(size_t)Mrows*Dc];

__device__ __forceinline__ void cp16(uint32_t dst, const void* src) {
    asm volatile("cp.async.cg.shared.global [%0], [%1], 16;\n" :: "r"(dst), "l"(src));
}
__device__ __forceinline__ float rsum16(float v) {
#pragma unroll
    for (int o = 8; o > 0; o >>= 1) v += __shfl_xor_sync(0xffffffffu, v, o);
    return v;
}

// ---------------------------------------------------------------------------
// fp32 -> fp16.  n multiple of 1024.
// ---------------------------------------------------------------------------
__global__ __launch_bounds__(256) void conv_hi_kernel(
    const float* __restrict__ x, __half* __restrict__ hi, int n)
{
    int i = (blockIdx.x*256 + threadIdx.x)*4;
    if (i >= n) return;
    float4 v = *(const float4*)&x[i];
    __half h[4];
    h[0] = __float2half_rn(v.x); h[1] = __float2half_rn(v.y);
    h[2] = __float2half_rn(v.z); h[3] = __float2half_rn(v.w);
    *(uint2*)&hi[i] = *(uint2*)h;
}

// 4 weight matrices in one launch (blockIdx.y selects src/dst)
__global__ __launch_bounds__(256) void conv4_kernel(
    const float* __restrict__ x0, const float* __restrict__ x1,
    const float* __restrict__ x2, const float* __restrict__ x3)
{
    const int sel = blockIdx.y;
    const float* x = (sel == 0) ? x0 : ((sel == 1) ? x1 : ((sel == 2) ? x2 : x3));
    __half* hi = (sel == 0) ? g_wqh : ((sel == 1) ? g_wkh : ((sel == 2) ? g_wvh : g_woh));
    int i = (blockIdx.x*256 + threadIdx.x)*4;
    float4 v = *(const float4*)&x[i];
    __half h[4];
    h[0] = __float2half_rn(v.x); h[1] = __float2half_rn(v.y);
    h[2] = __float2half_rn(v.z); h[3] = __float2half_rn(v.w);
    *(uint2*)&hi[i] = *(uint2*)h;
}

// lr_w [32][2048] -> g_lrwt [k][c] fp16, c in 0..127 (c>=32 zero), row stride Dc
__global__ __launch_bounds__(256) void lrt_kernel(const float* __restrict__ lr_w)
{
    int i = blockIdx.x*256 + threadIdx.x;   // 0 .. 2048*128-1
    int k = i >> 7, c = i & 127;
    g_lrwt[(size_t)k*Dc + c] =
        (c < 32) ? __float2half_rn(lr_w[(size_t)c*Dc + k]) : __half(0.f);
}

// ---------------------------------------------------------------------------
// Tensor-core GEMM: C = A @ B + bias ; single-pass fp16.
// mode 1: merged QKV + lr. grid.x = 49: tiles 0..47 = {Q,K,V} x 16 col-tiles;
//         tile 48 = lr (eta = sigmoid(acc + lr_b)/1024, scattered to g_eta).
// mode 0: output GEMM (A=g_xnh, W=g_woh, C=Cout fp32 row-major).
// CTA tile 128x128, BK=32, 3-stage cp.async, 8 warps of 64x32, 2 CTAs/SM.
// ---------------------------------------------------------------------------
#define LDSM4(R, addr) asm volatile( \
    "ldmatrix.sync.aligned.m8n8.x4.shared.b16 {%0,%1,%2,%3}, [%4];\n" \
    : "=r"((R)[0]), "=r"((R)[1]), "=r"((R)[2]), "=r"((R)[3]) : "r"(addr))
#define LDSM4T(R, addr) asm volatile( \
    "ldmatrix.sync.aligned.m8n8.x4.trans.shared.b16 {%0,%1,%2,%3}, [%4];\n" \
    : "=r"((R)[0]), "=r"((R)[1]), "=r"((R)[2]), "=r"((R)[3]) : "r"(addr))
#define MMA16816H(d, a, b0, b1) asm volatile( \
    "mma.sync.aligned.m16n8k16.row.col.f32.f16.f16.f32 " \
    "{%0,%1,%2,%3},{%4,%5,%6,%7},{%8,%9},{%0,%1,%2,%3};\n" \
    : "+f"((d)[0]), "+f"((d)[1]), "+f"((d)[2]), "+f"((d)[3]) \
    : "r"((a)[0]), "r"((a)[1]), "r"((a)[2]), "r"((a)[3]), "r"(b0), "r"(b1))

// smem: A 3x8192 | B 3x8192  = 49152 B
constexpr uint32_t R_A = 0, R_B = 24576;
constexpr uint32_t HG_SMEM = 49152;

__global__ __launch_bounds__(256, 2) void hgemm_kernel(
    const float* __restrict__ bias0, const float* __restrict__ bias1,
    const float* __restrict__ bias2, float* __restrict__ Cout, int mode)
{
    extern __shared__ __align__(16) unsigned char hsm[];
    const int tid = threadIdx.x, lane = tid & 31, wid = tid >> 5;
    const int wm = wid >> 2, wn = wid & 3;
    const int row0 = blockIdx.y*128, col0 = (blockIdx.x & 15)*128;

    const __half* Ah;
    const __half* Bm;
    const float* bias;
    float* C = nullptr;
    int sel = 0;
    if (mode == 1) {
        sel = blockIdx.x >> 4;                 // 0,1,2, or 3 (lr tile 48)
        Ah = g_ah;
        Bm = (sel == 0) ? g_wqh :
             ((sel == 1) ? g_wkh : ((sel == 2) ? g_wvh : g_lrwt));
        bias = (sel == 0) ? bias0 : ((sel == 1) ? bias1 : bias2);
        C = (sel == 0) ? g_q : ((sel == 1) ? g_k : g_v);
    } else {
        Ah = g_xnh; Bm = g_woh; bias = bias0; C = Cout;
    }
    const uint32_t sbase = (uint32_t)__cvta_generic_to_shared(hsm);

    const int ar0 = tid >> 2, ac0 = tid & 3;
    const int ar1 = (tid+256) >> 2, ac1 = tid & 3;
    const uint32_t aoff0 = (uint32_t)(ar0*64 + ((ac0 ^ ((ar0>>1)&3))*16));
    const uint32_t aoff1 = (uint32_t)(ar1*64 + ((ac1 ^ ((ar1>>1)&3))*16));
    const __half* gA0 = Ah + (size_t)(row0+ar0)*Dc + ac0*8;
    const __half* gA1 = Ah + (size_t)(row0+ar1)*Dc + ac1*8;
    const int pk = tid >> 3, pcb = tid & 7;
    const uint32_t boff0 = (uint32_t)(pk*256 + ((pcb     ^ (pk&7))*16));
    const uint32_t boff1 = (uint32_t)(pk*256 + (((pcb+8) ^ (pk&7))*16));
    const __half* gB = Bm + (size_t)pk*Dc + col0 + pcb*8;

    const int alr = lane & 15, alc = lane >> 4;
    uint32_t adA[4][2];
#pragma unroll
    for (int mi = 0; mi < 4; mi++) {
        int r = wm*64 + mi*16 + alr;
#pragma unroll
        for (int ks = 0; ks < 2; ks++) {
            int cch = ks*2 + alc;
            adA[mi][ks] = (uint32_t)(r*64 + ((cch ^ ((r>>1)&3))*16));
        }
    }
    const int bk0 = (lane & 7) + ((lane >> 3) & 1)*8;
    uint32_t adB[2][2];
#pragma unroll
    for (int nj = 0; nj < 2; nj++) {
        int cidx = wn*4 + nj*2 + ((lane >> 4) & 1);
#pragma unroll
        for (int ks = 0; ks < 2; ks++) {
            int kb = bk0 + ks*16;
            adB[nj][ks] = (uint32_t)(kb*256 + ((cidx ^ (kb & 7))*16));
        }
    }

    float acc[4][4][4];
#pragma unroll
    for (int i = 0; i < 4; i++)
#pragma unroll
        for (int j = 0; j < 4; j++)
#pragma unroll
            for (int k = 0; k < 4; k++) acc[i][j][k] = 0.f;

    constexpr int KT = Dc / 32;   // 64 iterations

    auto prefetch = [&](int kt) {
        const uint32_t so = (uint32_t)(kt % 3)*8192;
        const size_t gAo = (size_t)kt*32;
        const size_t gBo = (size_t)kt*32*Dc;
        cp16(sbase + R_A + so + aoff0, gA0 + gAo);
        cp16(sbase + R_A + so + aoff1, gA1 + gAo);
        cp16(sbase + R_B + so + boff0, gB + gBo);
        cp16(sbase + R_B + so + boff1, gB + gBo + 64);
        asm volatile("cp.async.commit_group;\n");
    };

    prefetch(0);
    prefetch(1);

    for (int kt = 0; kt < KT; kt++) {
        asm volatile("cp.async.wait_group 1;\n");
        __syncthreads();
        if (kt + 2 < KT) prefetch(kt + 2);
        else asm volatile("cp.async.commit_group;\n");

        const uint32_t so = (uint32_t)(kt % 3)*8192;
#pragma unroll
        for (int ks = 0; ks < 2; ks++) {
            uint32_t ar[4][4], bb[2][4];
#pragma unroll
            for (int mi = 0; mi < 4; mi++)
                LDSM4(ar[mi], sbase + R_A + so + adA[mi][ks]);
#pragma unroll
            for (int nj = 0; nj < 2; nj++)
                LDSM4T(bb[nj], sbase + R_B + so + adB[nj][ks]);
#pragma unroll
            for (int mi = 0; mi < 4; mi++) {
#pragma unroll
                for (int ni = 0; ni < 4; ni++) {
                    const int q = ni >> 1, hb = (ni & 1)*2;
                    MMA16816H(acc[mi][ni], ar[mi], bb[q][hb], bb[q][hb+1]);
                }
            }
        }
    }

    // ---- epilogue ----
    const int g = lane >> 2, t2 = (lane & 3)*2;
    if (mode == 1 && sel == 3) {
        // lr tile: eta = sigmoid(acc + lr_b)/1024 for cols < 32 (wn==0 warps)
        if (wn == 0) {
            const float* lrb = (const float*)Cout;   // lr_b smuggled via Cout
#pragma unroll
            for (int mi = 0; mi < 4; mi++) {
                const int r1 = row0 + wm*64 + mi*16 + g;
                const int r2 = r1 + 8;
#pragma unroll
                for (int ni = 0; ni < 4; ni++) {
                    const int col = ni*8 + t2;       // 0..30
                    const float bl0 = lrb[col], bl1 = lrb[col+1];
#pragma unroll
                    for (int rr = 0; rr < 2; rr++) {
                        const int row = rr ? r2 : r1;
                        const int b = row >> 12, l = row & 4095;
                        const int n = l >> 4, kk = l & 15;
                        const float x0 = acc[mi][ni][rr*2+0] + bl0;
                        const float x1 = acc[mi][ni][rr*2+1] + bl1;
                        const float s0 = 1.f/(1.f+expf(-x0)) * (1.f/1024.f);
                        const float s1 = 1.f/(1.f+expf(-x1)) * (1.f/1024.f);
                        g_eta[(((size_t)(b*Hh + col  ))*NMBc + n)*Kc + kk] = s0;
                        g_eta[(((size_t)(b*Hh + col+1))*NMBc + n)*Kc + kk] = s1;
                    }
                }
            }
        }
        return;
    }
#pragma unroll
    for (int mi = 0; mi < 4; mi++) {
        const int r1 = row0 + wm*64 + mi*16 + g;
        const int r2 = r1 + 8;
#pragma unroll
        for (int ni = 0; ni < 4; ni++) {
            const int col = col0 + wn*32 + ni*8 + t2;
            const float2 bv = *(const float2*)&bias[col];
            float2 v0 = make_float2(acc[mi][ni][0] + bv.x, acc[mi][ni][1] + bv.y);
            float2 v1 = make_float2(acc[mi][ni][2] + bv.x, acc[mi][ni][3] + bv.y);
            if (mode == 0) {
                *(float2*)&C[(size_t)r1*Dc + col] = v0;
                *(float2*)&C[(size_t)r2*Dc + col] = v1;
            } else {
                const int h = col >> 6, d = col & 63;
                {
                    int b = r1 >> 12, l = r1 & 4095, n = l >> 4, kk = l & 15;
                    size_t o = ((((size_t)(b*Hh + h))*NMBc + n)*Kc + kk)*HDc + d;
                    *(float2*)&C[o] = v0;
                }
                {
                    int b = r2 >> 12, l = r2 & 4095, n = l >> 4, kk = l & 15;
                    size_t o = ((((size_t)(b*Hh + h))*NMBc + n)*Kc + kk)*HDc + d;
                    *(float2*)&C[o] = v1;
                }
            }
        }
    }
}

// ---------------------------------------------------------------------------
// preattn: per tile (bh,n): normalize Q,K; XV residual-LN; Attn' = tril(q@kT)+1
// ---------------------------------------------------------------------------
__global__ __launch_bounds__(256) void preattn_kernel(
    const float* __restrict__ tnw, const float* __restrict__ tnb)
{
    __shared__ __align__(16) float qs[1024];
    __shared__ __align__(16) float ksT[64*17];
    const int t = blockIdx.x;                 // bh*NMBc + n
    const int h = (t >> 8) & 31;
    const size_t base = (size_t)t * 1024;
    const int tid = threadIdx.x, r = tid >> 4, i2 = tid & 15, c4 = i2*4;

    float4 q = *(const float4*)&g_q[base + r*64 + c4];
    float4 k = *(const float4*)&g_k[base + r*64 + c4];
    float4 v = *(const float4*)&g_v[base + r*64 + c4];

    float sq = rsum16(q.x*q.x + q.y*q.y + q.z*q.z + q.w*q.w);
    float qi = 1.f / fmaxf(sqrtf(sq), 1e-12f);
    q.x *= qi; q.y *= qi; q.z *= qi; q.w *= qi;

    float sk = rsum16(k.x*k.x + k.y*k.y + k.z*k.z + k.w*k.w);
    float ki = 1.f / fmaxf(sqrtf(sk), 1e-12f);
    k.x *= ki; k.y *= ki; k.z *= ki; k.w *= ki;

    float dx = v.x-k.x, dy = v.y-k.y, dz = v.z-k.z, dw = v.w-k.w;
    float mu = rsum16(dx+dy+dz+dw) * (1.f/64.f);
    float ex = dx-mu, ey = dy-mu, ez = dz-mu, ew = dw-mu;
    float ss = rsum16(ex*ex + ey*ey + ez*ez + ew*ew);
    float id = 1.f / (sqrtf(ss * (1.f/63.f)) + 1e-8f);    // ddof=1
    const float4 lw = *(const float4*)&tnw[h*64 + c4];
    const float4 lb = *(const float4*)&tnb[h*64 + c4];
    float4 nv;
    nv.x = lw.x*ex*id + lb.x + k.x;
    nv.y = lw.y*ey*id + lb.y + k.y;
    nv.z = lw.z*ez*id + lb.z + k.z;
    nv.w = lw.w*ew*id + lb.w + k.w;

    *(float4*)&g_q[base + r*64 + c4] = q;
    *(float4*)&g_k[base + r*64 + c4] = k;
    *(float4*)&g_v[base + r*64 + c4] = nv;

    *(float4*)&qs[r*64 + c4] = q;
    ksT[(c4+0)*17 + r] = k.x;
    ksT[(c4+1)*17 + r] = k.y;
    ksT[(c4+2)*17 + r] = k.z;
    ksT[(c4+3)*17 + r] = k.w;
    __syncthreads();

    // attn'[r][j] = (j<=r) ? (q[r].k[j] + 1) : 0
    float d = 0.f;
#pragma unroll 8
    for (int t2 = 0; t2 < 64; t2++) d += qs[r*64 + t2] * ksT[t2*17 + i2];
    g_attn[(size_t)t*256 + r*16 + i2] = (i2 <= r) ? (d + 1.f) : 0.f;
}

// ---------------------------------------------------------------------------
// Sequential TTT scan (R11 proven). One CTA per (b,h). 256 threads.
// ---------------------------------------------------------------------------
__global__ __launch_bounds__(256) void scan_kernel(
    const float* __restrict__ W1g, const float* __restrict__ b1g,
    const float* __restrict__ tnw, const float* __restrict__ tnb)
{
    __shared__ __align__(16) float W1s[64*64];
    __shared__ __align__(16) float xqs[1024];
    __shared__ __align__(16) float xks[1024];
    __shared__ __align__(16) float xvs[1024];
    __shared__ __align__(16) float grads[1024];
    __shared__ __align__(16) float xkTs[64*17];
    __shared__ __align__(16) float Ms[256];
    __shared__ float b1s[64], lnw[64], lnb[64], etas[16];

    const int bh = blockIdx.x;
    const int b = bh >> 5, h = bh & 31;
    const int tid = threadIdx.x;
    const int r = tid >> 4, i2 = tid & 15, c4 = i2*4;
    const int cu = tid & 63, qg = tid >> 6;         // update layout

    for (int i = tid; i < 4096; i += 256) W1s[i] = W1g[(size_t)h*4096 + i];
    if (tid < 64) {
        b1s[tid] = b1g[h*64 + tid];
        lnw[tid] = tnw[h*64 + tid];
        lnb[tid] = tnb[h*64 + tid];
    }

    const size_t tile0 = (size_t)bh * (NMBc * 1024);
    const size_t atn0  = (size_t)bh * (NMBc * 256);

    for (int j = 0; j < 4; j++) {
        int idx = tid + j*256;
        float vq = g_q[tile0+idx];
        float vk = g_k[tile0+idx];
        float vv = g_v[tile0+idx];
        xqs[idx] = vq; xks[idx] = vk; xvs[idx] = vv;
        xkTs[(idx & 63)*17 + (idx >> 6)] = vk;
    }
    Ms[tid] = g_attn[atn0 + tid];
    if (tid < 16) etas[tid] = g_eta[(size_t)bh*NMBc*Kc + tid];
    __syncthreads();

    for (int n = 0; n < NMBc; n++) {
        float rq[4], rk[4], rv[4], ra = 0.f, re = 0.f;
        const bool pf = (n + 1 < NMBc);
        if (pf) {
            const size_t tb = tile0 + (size_t)(n+1)*1024;
#pragma unroll
            for (int j = 0; j < 4; j++) {
                rq[j] = g_q[tb + tid + j*256];
                rk[j] = g_k[tb + tid + j*256];
                rv[j] = g_v[tb + tid + j*256];
            }
            ra = g_attn[atn0 + (size_t)(n+1)*256 + tid];
            if (tid < 16) re = g_eta[((size_t)bh*NMBc + n+1)*Kc + tid];
        }

        const float4 lw = *(const float4*)&lnw[c4];
        const float4 lb = *(const float4*)&lnb[c4];
        const float4 bb = *(const float4*)&b1s[c4];

        // ---- Phase A: Z1 -> LN stats -> grad (eta folded) ----
        {
            float4 z = bb;
#pragma unroll 8
            for (int k = 0; k < 64; k++) {
                float a = xks[r*64 + k];
                float4 w = *(const float4*)&W1s[k*64 + c4];
                z.x += a*w.x; z.y += a*w.y; z.z += a*w.z; z.w += a*w.w;
            }
            float mu = rsum16(z.x+z.y+z.z+z.w) * (1.f/64.f);
            float dx = z.x-mu, dy = z.y-mu, dz = z.z-mu, dw = z.w-mu;
            float var = rsum16(dx*dx+dy*dy+dz*dz+dw*dw) * (1.f/64.f);
            float stdv = sqrtf(var + 1e-6f);
            float inv = 1.f/stdv;
            float xhx = dx*inv, xhy = dy*inv, xhz = dz*inv, xhw = dw*inv;
            const float4 kv = *(const float4*)&xks[r*64 + c4];
            const float4 vv = *(const float4*)&xvs[r*64 + c4];
            float gx = (lw.x*xhx + lb.x - (vv.x - kv.x))*lw.x;
            float gy = (lw.y*xhy + lb.y - (vv.y - kv.y))*lw.y;
            float gz = (lw.z*xhz + lb.z - (vv.z - kv.z))*lw.z;
            float gw = (lw.w*xhw + lb.w - (vv.w - kv.w))*lw.w;
            float s1 = rsum16(gx+gy+gz+gw);
            float s2 = rsum16(gx*xhx + gy*xhy + gz*xhz + gw*xhw);
            float sc = etas[r] * (1.f/(64.f*stdv));
            float4 g4;
            g4.x = (64.f*gx - s1 - xhx*s2)*sc;
            g4.y = (64.f*gy - s1 - xhy*s2)*sc;
            g4.z = (64.f*gz - s1 - xhz*s2)*sc;
            g4.w = (64.f*gw - s1 - xhw*s2)*sc;
            *(float4*)&grads[r*64 + c4] = g4;
        }
        __syncthreads();

        // ---- Phase B: Z1_bar = xq@W1 + b1 - A'@eg -> LN -> output ----
        {
            float4 zb = bb;
#pragma unroll 8
            for (int k = 0; k < 64; k++) {
                float a = xqs[r*64 + k];
                float4 w = *(const float4*)&W1s[k*64 + c4];
                zb.x += a*w.x; zb.y += a*w.y; zb.z += a*w.z; zb.w += a*w.w;
            }
#pragma unroll
            for (int j = 0; j < 16; j++) {
                float m = Ms[r*16 + j];
                float4 g4 = *(const float4*)&grads[j*64 + c4];
                zb.x -= m*g4.x; zb.y -= m*g4.y; zb.z -= m*g4.z; zb.w -= m*g4.w;
            }
            float mu2 = rsum16(zb.x+zb.y+zb.z+zb.w) * (1.f/64.f);
            float ex = zb.x-mu2, ey = zb.y-mu2, ez = zb.z-mu2, ew = zb.w-mu2;
            float var2 = rsum16(ex*ex+ey*ey+ez*ez+ew*ew) * (1.f/64.f);
            float inv2 = rsqrtf(var2 + 1e-6f);
            const float4 q4 = *(const float4*)&xqs[r*64 + c4];
            float4 out;
            out.x = q4.x + ex*inv2*lw.x + lb.x;
            out.y = q4.y + ey*inv2*lw.y + lb.y;
            out.z = q4.z + ez*inv2*lw.z + lb.z;
            out.w = q4.w + ew*inv2*lw.w + lb.w;
            *(float4*)&g_y[((size_t)b*Lc + n*Kc + r)*Dc + h*HDc + c4] = out;
        }
        __syncthreads();

        // ---- Phase C: state update (W1 -= xkT@eg, b1 -= sum eg) ----
        {
            float greg[16];
#pragma unroll
            for (int j = 0; j < 16; j++) greg[j] = grads[j*64 + cu];
            if (qg == 0) {
                float s = 0.f;
#pragma unroll
                for (int j = 0; j < 16; j++) s += greg[j];
                b1s[cu] -= s;
            }
#pragma unroll
            for (int kk = 0; kk < 16; kk++) {
                int k = qg*16 + kk;
                float s = 0.f;
#pragma unroll
                for (int j = 0; j < 16; j++) s += xkTs[k*17 + j] * greg[j];
                W1s[k*64 + cu] -= s;
            }
        }
        __syncthreads();

        // ---- commit prefetched tile n+1 ----
        if (pf) {
#pragma unroll
            for (int j = 0; j < 4; j++) {
                int idx = tid + j*256;
                xqs[idx] = rq[j];
                xks[idx] = rk[j];
                xvs[idx] = rv[j];
                xkTs[(idx & 63)*17 + (idx >> 6)] = rk[j];
            }
            Ms[tid] = ra;
            if (tid < 16) etas[tid] = re;
        }
        __syncthreads();
    }
}

// ---------------------------------------------------------------------------
// Post layernorm over D=2048 per token; emits fp16 directly.
// ---------------------------------------------------------------------------
__global__ __launch_bounds__(256) void postnorm_kernel(
    const float* __restrict__ pw, const float* __restrict__ pb)
{
    __shared__ float red[8];
    __shared__ float smu, svar;
    const int row = blockIdx.x, tid = threadIdx.x;
    const int lane = tid & 31, wid = tid >> 5;
    const float* x = g_y + (size_t)row*Dc;

    float v[8];
    *(float4*)(v)   = *(const float4*)&x[tid*8];
    *(float4*)(v+4) = *(const float4*)&x[tid*8+4];

    float s = v[0]+v[1]+v[2]+v[3]+v[4]+v[5]+v[6]+v[7];
#pragma unroll
    for (int o = 16; o > 0; o >>= 1) s += __shfl_xor_sync(0xffffffffu, s, o);
    if (lane == 0) red[wid] = s;
    __syncthreads();
    if (tid == 0) {
        float t = 0.f;
#pragma unroll
        for (int i = 0; i < 8; i++) t += red[i];
        smu = t * (1.f/2048.f);
    }
    __syncthreads();
    float mu = smu;

    float ss = 0.f;
#pragma unroll
    for (int i = 0; i < 8; i++) { float d = v[i]-mu; ss += d*d; }
#pragma unroll
    for (int o = 16; o > 0; o >>= 1) ss += __shfl_xor_sync(0xffffffffu, ss, o);
    if (lane == 0) red[wid] = ss;
    __syncthreads();
    if (tid == 0) {
        float t = 0.f;
#pragma unroll
        for (int i = 0; i < 8; i++) t += red[i];
        svar = t * (1.f/2048.f);
    }
    __syncthreads();
    float rstd = rsqrtf(svar + 1e-6f);

    __half hb[8];
#pragma unroll
    for (int i = 0; i < 8; i++) {
        int cc = tid*8 + i;
        float y = (v[i]-mu)*rstd*pw[cc] + pb[cc];
        hb[i] = __float2half_rn(y);
    }
    *(uint4*)&g_xnh[(size_t)row*Dc + tid*8] = *(uint4*)hb;
}

// ---------------------------------------------------------------------------
extern "C" void kernel_launch(void* const* d_in, const int* in_sizes, int n_in,
                              void* d_out, int out_size)
{
    (void)in_sizes; (void)n_in; (void)out_size;
    const float* hs    = (const float*)d_in[0];
    const float* wq_w  = (const float*)d_in[1];
    const float* wq_b  = (const float*)d_in[2];
    const float* wk_w  = (const float*)d_in[3];
    const float* wk_b  = (const float*)d_in[4];
    const float* wv_w  = (const float*)d_in[5];
    const float* wv_b  = (const float*)d_in[6];
    const float* wo_w  = (const float*)d_in[7];
    const float* wo_b  = (const float*)d_in[8];
    const float* tnw   = (const float*)d_in[9];
    const float* tnb   = (const float*)d_in[10];
    const float* lr_w  = (const float*)d_in[11];
    const float* lr_b  = (const float*)d_in[12];
    const float* W1    = (const float*)d_in[13];
    const float* b1    = (const float*)d_in[14];
    const float* pnw   = (const float*)d_in[15];
    const float* pnb   = (const float*)d_in[16];

    __half* ah;
    cudaGetSymbolAddress((void**)&ah, g_ah);

    cudaFuncSetAttribute(hgemm_kernel,
                         cudaFuncAttributeMaxDynamicSharedMemorySize, HG_SMEM);

    const int nA = Mrows*Dc;     // 16.7M
    const int nW = Dc*Dc;        // 4.2M
    conv_hi_kernel<<<nA/1024, 256>>>(hs, ah, nA);
    conv4_kernel<<<dim3(nW/1024, 4), 256>>>(wq_w, wk_w, wv_w, wo_w);
    lrt_kernel<<<(Dc*128)/256, 256>>>(lr_w);

    // merged QKV + lr GEMM: tiles 0..47 = QKV, tile 48 = lr (eta)
    hgemm_kernel<<<dim3(49, 64), 256, HG_SMEM>>>(wq_b, wk_b, wv_b,
                                                 (float*)lr_b, 1);
    preattn_kernel<<<Bb*Hh*NMBc, 256>>>(tnw, tnb);
    scan_kernel<<<Bb*Hh, 256>>>(W1, b1, tnw, tnb);
    postnorm_kernel<<<Mrows, 256>>>(pnw, pnb);
    hgemm_kernel<<<dim3(16, 64), 256, HG_SMEM>>>(wo_b, nullptr, nullptr,
                                                 (float*)d_out, 0);
}

// round 17
// speedup vs baseline: 1.5375x; 1.5375x over previous
#include <cuda_runtime.h>
#include <cuda_fp16.h>
#include <math.h>
#include <stdint.h>

// Problem constants (fixed shapes)
constexpr int Bb  = 2;
constexpr int Lc  = 4096;
constexpr int Dc  = 2048;
constexpr int Hh  = 32;
constexpr int Kc  = 16;
constexpr int HDc = 64;
constexpr int NMBc = 256;           // L / K
constexpr int Mrows = Bb * Lc;      // 8192

// Scratch (device globals; allocation in kernel_launch is forbidden)
__device__ float g_q  [(size_t)Bb*Hh*NMBc*Kc*HDc];   // scan layout [b][h][n][k][d]
__device__ float g_k  [(size_t)Bb*Hh*NMBc*Kc*HDc];
__device__ float g_v  [(size_t)Bb*Hh*NMBc*Kc*HDc];
__device__ float g_eta[(size_t)Bb*Hh*NMBc*Kc];
__device__ float g_attn[(size_t)Bb*Hh*NMBc*Kc*Kc];  // pre-masked (attn+1), tril
__device__ float g_y  [(size_t)Bb*Lc*Dc];            // scan output, token layout

// fp16 operands for tensor-core GEMMs (single-pass fp16)
__device__ __half g_ah [(size_t)Mrows*Dc];
__device__ __half g_wqh[(size_t)Dc*Dc];
__device__ __half g_wkh[(size_t)Dc*Dc];
__device__ __half g_wvh[(size_t)Dc*Dc];
__device__ __half g_woh[(size_t)Dc*Dc];
__device__ __half g_xnh[(size_t)Mrows*Dc];

__device__ __forceinline__ void cp16(uint32_t dst, const void* src) {
    asm volatile("cp.async.cg.shared.global [%0], [%1], 16;\n" :: "r"(dst), "l"(src));
}
__device__ __forceinline__ float rsum16(float v) {
#pragma unroll
    for (int o = 8; o > 0; o >>= 1) v += __shfl_xor_sync(0xffffffffu, v, o);
    return v;
}

// ---------------------------------------------------------------------------
// fp32 -> fp16.  n multiple of 1024.
// ---------------------------------------------------------------------------
__global__ __launch_bounds__(256) void conv_hi_kernel(
    const float* __restrict__ x, __half* __restrict__ hi, int n)
{
    int i = (blockIdx.x*256 + threadIdx.x)*4;
    if (i >= n) return;
    float4 v = *(const float4*)&x[i];
    __half h[4];
    h[0] = __float2half_rn(v.x); h[1] = __float2half_rn(v.y);
    h[2] = __float2half_rn(v.z); h[3] = __float2half_rn(v.w);
    *(uint2*)&hi[i] = *(uint2*)h;
}

// 4 weight matrices in one launch (blockIdx.y selects src/dst)
__global__ __launch_bounds__(256) void conv4_kernel(
    const float* __restrict__ x0, const float* __restrict__ x1,
    const float* __restrict__ x2, const float* __restrict__ x3)
{
    const int sel = blockIdx.y;
    const float* x = (sel == 0) ? x0 : ((sel == 1) ? x1 : ((sel == 2) ? x2 : x3));
    __half* hi = (sel == 0) ? g_wqh : ((sel == 1) ? g_wkh : ((sel == 2) ? g_wvh : g_woh));
    int i = (blockIdx.x*256 + threadIdx.x)*4;
    float4 v = *(const float4*)&x[i];
    __half h[4];
    h[0] = __float2half_rn(v.x); h[1] = __float2half_rn(v.y);
    h[2] = __float2half_rn(v.z); h[3] = __float2half_rn(v.w);
    *(uint2*)&hi[i] = *(uint2*)h;
}

// ---------------------------------------------------------------------------
// Tensor-core GEMM (R11 proven, FROZEN): C = A @ B + bias ; single-pass fp16.
// mode 1: merged QKV (sel = blockIdx.x>>4), permuted epilogue to scan layout.
// mode 0: output GEMM (A=g_xnh, W=g_woh, C=Cout fp32 row-major).
// CTA tile 128x128, BK=32, 3-stage cp.async, 8 warps of 64x32, 2 CTAs/SM.
// ---------------------------------------------------------------------------
#define LDSM4(R, addr) asm volatile( \
    "ldmatrix.sync.aligned.m8n8.x4.shared.b16 {%0,%1,%2,%3}, [%4];\n" \
    : "=r"((R)[0]), "=r"((R)[1]), "=r"((R)[2]), "=r"((R)[3]) : "r"(addr))
#define LDSM4T(R, addr) asm volatile( \
    "ldmatrix.sync.aligned.m8n8.x4.trans.shared.b16 {%0,%1,%2,%3}, [%4];\n" \
    : "=r"((R)[0]), "=r"((R)[1]), "=r"((R)[2]), "=r"((R)[3]) : "r"(addr))
#define MMA16816H(d, a, b0, b1) asm volatile( \
    "mma.sync.aligned.m16n8k16.row.col.f32.f16.f16.f32 " \
    "{%0,%1,%2,%3},{%4,%5,%6,%7},{%8,%9},{%0,%1,%2,%3};\n" \
    : "+f"((d)[0]), "+f"((d)[1]), "+f"((d)[2]), "+f"((d)[3]) \
    : "r"((a)[0]), "r"((a)[1]), "r"((a)[2]), "r"((a)[3]), "r"(b0), "r"(b1))

// smem: A 3x8192 | B 3x8192  = 49152 B
constexpr uint32_t R_A = 0, R_B = 24576;
constexpr uint32_t HG_SMEM = 49152;

__global__ __launch_bounds__(256, 2) void hgemm_kernel(
    const float* __restrict__ bias0, const float* __restrict__ bias1,
    const float* __restrict__ bias2, float* __restrict__ Cout, int mode)
{
    extern __shared__ __align__(16) unsigned char hsm[];
    const int tid = threadIdx.x, lane = tid & 31, wid = tid >> 5;
    const int wm = wid >> 2, wn = wid & 3;
    const int row0 = blockIdx.y*128, col0 = (blockIdx.x & 15)*128;

    const __half* Ah;
    const __half* Bm;
    const float* bias;
    float* C;
    if (mode == 1) {
        const int sel = blockIdx.x >> 4;
        Ah = g_ah;
        Bm = (sel == 0) ? g_wqh : ((sel == 1) ? g_wkh : g_wvh);
        bias = (sel == 0) ? bias0 : ((sel == 1) ? bias1 : bias2);
        C = (sel == 0) ? g_q : ((sel == 1) ? g_k : g_v);
    } else {
        Ah = g_xnh; Bm = g_woh; bias = bias0; C = Cout;
    }
    const uint32_t sbase = (uint32_t)__cvta_generic_to_shared(hsm);

    const int ar0 = tid >> 2, ac0 = tid & 3;
    const int ar1 = (tid+256) >> 2, ac1 = tid & 3;
    const uint32_t aoff0 = (uint32_t)(ar0*64 + ((ac0 ^ ((ar0>>1)&3))*16));
    const uint32_t aoff1 = (uint32_t)(ar1*64 + ((ac1 ^ ((ar1>>1)&3))*16));
    const __half* gA0 = Ah + (size_t)(row0+ar0)*Dc + ac0*8;
    const __half* gA1 = Ah + (size_t)(row0+ar1)*Dc + ac1*8;
    const int pk = tid >> 3, pcb = tid & 7;
    const uint32_t boff0 = (uint32_t)(pk*256 + ((pcb     ^ (pk&7))*16));
    const uint32_t boff1 = (uint32_t)(pk*256 + (((pcb+8) ^ (pk&7))*16));
    const __half* gB = Bm + (size_t)pk*Dc + col0 + pcb*8;

    const int alr = lane & 15, alc = lane >> 4;
    uint32_t adA[4][2];
#pragma unroll
    for (int mi = 0; mi < 4; mi++) {
        int r = wm*64 + mi*16 + alr;
#pragma unroll
        for (int ks = 0; ks < 2; ks++) {
            int cch = ks*2 + alc;
            adA[mi][ks] = (uint32_t)(r*64 + ((cch ^ ((r>>1)&3))*16));
        }
    }
    const int bk0 = (lane & 7) + ((lane >> 3) & 1)*8;
    uint32_t adB[2][2];
#pragma unroll
    for (int nj = 0; nj < 2; nj++) {
        int cidx = wn*4 + nj*2 + ((lane >> 4) & 1);
#pragma unroll
        for (int ks = 0; ks < 2; ks++) {
            int kb = bk0 + ks*16;
            adB[nj][ks] = (uint32_t)(kb*256 + ((cidx ^ (kb & 7))*16));
        }
    }

    float acc[4][4][4];
#pragma unroll
    for (int i = 0; i < 4; i++)
#pragma unroll
        for (int j = 0; j < 4; j++)
#pragma unroll
            for (int k = 0; k < 4; k++) acc[i][j][k] = 0.f;

    constexpr int KT = Dc / 32;   // 64 iterations

    auto prefetch = [&](int kt) {
        const uint32_t so = (uint32_t)(kt % 3)*8192;
        const size_t gAo = (size_t)kt*32;
        const size_t gBo = (size_t)kt*32*Dc;
        cp16(sbase + R_A + so + aoff0, gA0 + gAo);
        cp16(sbase + R_A + so + aoff1, gA1 + gAo);
        cp16(sbase + R_B + so + boff0, gB + gBo);
        cp16(sbase + R_B + so + boff1, gB + gBo + 64);
        asm volatile("cp.async.commit_group;\n");
    };

    prefetch(0);
    prefetch(1);

    for (int kt = 0; kt < KT; kt++) {
        asm volatile("cp.async.wait_group 1;\n");
        __syncthreads();
        if (kt + 2 < KT) prefetch(kt + 2);
        else asm volatile("cp.async.commit_group;\n");

        const uint32_t so = (uint32_t)(kt % 3)*8192;
#pragma unroll
        for (int ks = 0; ks < 2; ks++) {
            uint32_t ar[4][4], bb[2][4];
#pragma unroll
            for (int mi = 0; mi < 4; mi++)
                LDSM4(ar[mi], sbase + R_A + so + adA[mi][ks]);
#pragma unroll
            for (int nj = 0; nj < 2; nj++)
                LDSM4T(bb[nj], sbase + R_B + so + adB[nj][ks]);
#pragma unroll
            for (int mi = 0; mi < 4; mi++) {
#pragma unroll
                for (int ni = 0; ni < 4; ni++) {
                    const int q = ni >> 1, hb = (ni & 1)*2;
                    MMA16816H(acc[mi][ni], ar[mi], bb[q][hb], bb[q][hb+1]);
                }
            }
        }
    }

    // ---- epilogue ----
    const int g = lane >> 2, t2 = (lane & 3)*2;
#pragma unroll
    for (int mi = 0; mi < 4; mi++) {
        const int r1 = row0 + wm*64 + mi*16 + g;
        const int r2 = r1 + 8;
#pragma unroll
        for (int ni = 0; ni < 4; ni++) {
            const int col = col0 + wn*32 + ni*8 + t2;
            const float2 bv = *(const float2*)&bias[col];
            float2 v0 = make_float2(acc[mi][ni][0] + bv.x, acc[mi][ni][1] + bv.y);
            float2 v1 = make_float2(acc[mi][ni][2] + bv.x, acc[mi][ni][3] + bv.y);
            if (mode == 0) {
                *(float2*)&C[(size_t)r1*Dc + col] = v0;
                *(float2*)&C[(size_t)r2*Dc + col] = v1;
            } else {
                const int h = col >> 6, d = col & 63;
                {
                    int b = r1 >> 12, l = r1 & 4095, n = l >> 4, kk = l & 15;
                    size_t o = ((((size_t)(b*Hh + h))*NMBc + n)*Kc + kk)*HDc + d;
                    *(float2*)&C[o] = v0;
                }
                {
                    int b = r2 >> 12, l = r2 & 4095, n = l >> 4, kk = l & 15;
                    size_t o = ((((size_t)(b*Hh + h))*NMBc + n)*Kc + kk)*HDc + d;
                    *(float2*)&C[o] = v1;
                }
            }
        }
    }
}

// ---------------------------------------------------------------------------
// lr GEMM: eta[t][h] = sigmoid(hs[t] . lr_w[h] + lr_b[h]) / 1024
// 64 tokens x 32 heads per CTA (R11 mapping), software-pipelined: next K-tile
// global loads are issued before the current tile's compute so their latency
// hides under the FMA loop.
// ---------------------------------------------------------------------------
__global__ __launch_bounds__(256) void lr_gemm_kernel(
    const float* __restrict__ hs, const float* __restrict__ lr_w,
    const float* __restrict__ lr_b)
{
    __shared__ float As[32][65];   // [k][token]
    __shared__ float Ws[32][32];   // [k][head]
    const int tid = threadIdx.x;
    const int t0 = blockIdx.x*64;
    const int r0 = (tid >> 4)*4;        // 4 tokens
    const int c0 = (tid & 15)*2;        // 2 heads

    float acc[4][2];
#pragma unroll
    for (int i = 0; i < 4; i++) { acc[i][0] = 0.f; acc[i][1] = 0.f; }

    const int lrow = tid >> 2;              // 0..63
    const int lcol = (tid & 3)*8;           // 0,8,16,24
    const float* aptr = hs + (size_t)(t0+lrow)*Dc + lcol;
    const int wh = tid >> 5 /*unused*/;
    (void)wh;

    // preload k0 = 0
    float4 a0 = *(const float4*)&aptr[0];
    float4 a1 = *(const float4*)&aptr[4];
    float wv[4];
#pragma unroll
    for (int j = 0; j < 4; j++) {
        int i = tid + j*256;
        wv[j] = lr_w[(size_t)(i >> 5)*Dc + (i & 31)];
    }

    for (int k0 = 0; k0 < Dc; k0 += 32) {
        __syncthreads();            // previous compute finished reading smem
        As[lcol+0][lrow] = a0.x; As[lcol+1][lrow] = a0.y;
        As[lcol+2][lrow] = a0.z; As[lcol+3][lrow] = a0.w;
        As[lcol+4][lrow] = a1.x; As[lcol+5][lrow] = a1.y;
        As[lcol+6][lrow] = a1.z; As[lcol+7][lrow] = a1.w;
#pragma unroll
        for (int j = 0; j < 4; j++) {
            int i = tid + j*256;
            Ws[i & 31][i >> 5] = wv[j];
        }
        __syncthreads();

        // issue next tile's loads; latency hides under compute below
        if (k0 + 32 < Dc) {
            a0 = *(const float4*)&aptr[k0 + 32];
            a1 = *(const float4*)&aptr[k0 + 36];
#pragma unroll
            for (int j = 0; j < 4; j++) {
                int i = tid + j*256;
                wv[j] = lr_w[(size_t)(i >> 5)*Dc + k0 + 32 + (i & 31)];
            }
        }

#pragma unroll 8
        for (int k = 0; k < 32; k++) {
            float w0 = Ws[k][c0], w1 = Ws[k][c0+1];
#pragma unroll
            for (int i = 0; i < 4; i++) {
                float a = As[k][r0+i];
                acc[i][0] += a*w0;
                acc[i][1] += a*w1;
            }
        }
    }

#pragma unroll
    for (int i = 0; i < 4; i++) {
        const int t = t0 + r0 + i;
        const int b = t >> 12, l = t & 4095, n = l >> 4, kk = l & 15;
#pragma unroll
        for (int j = 0; j < 2; j++) {
            const int h = c0 + j;
            float x = acc[i][j] + lr_b[h];
            float sig = 1.f/(1.f+expf(-x));
            g_eta[(((size_t)(b*Hh + h))*NMBc + n)*Kc + kk] = sig * (1.f/1024.f);
        }
    }
}

// ---------------------------------------------------------------------------
// preattn: per tile (bh,n): normalize Q,K; XV residual-LN; Attn' = tril(q@kT)+1
// ---------------------------------------------------------------------------
__global__ __launch_bounds__(256) void preattn_kernel(
    const float* __restrict__ tnw, const float* __restrict__ tnb)
{
    __shared__ __align__(16) float qs[1024];
    __shared__ __align__(16) float ksT[64*17];
    const int t = blockIdx.x;                 // bh*NMBc + n
    const int h = (t >> 8) & 31;
    const size_t base = (size_t)t * 1024;
    const int tid = threadIdx.x, r = tid >> 4, i2 = tid & 15, c4 = i2*4;

    float4 q = *(const float4*)&g_q[base + r*64 + c4];
    float4 k = *(const float4*)&g_k[base + r*64 + c4];
    float4 v = *(const float4*)&g_v[base + r*64 + c4];

    float sq = rsum16(q.x*q.x + q.y*q.y + q.z*q.z + q.w*q.w);
    float qi = 1.f / fmaxf(sqrtf(sq), 1e-12f);
    q.x *= qi; q.y *= qi; q.z *= qi; q.w *= qi;

    float sk = rsum16(k.x*k.x + k.y*k.y + k.z*k.z + k.w*k.w);
    float ki = 1.f / fmaxf(sqrtf(sk), 1e-12f);
    k.x *= ki; k.y *= ki; k.z *= ki; k.w *= ki;

    float dx = v.x-k.x, dy = v.y-k.y, dz = v.z-k.z, dw = v.w-k.w;
    float mu = rsum16(dx+dy+dz+dw) * (1.f/64.f);
    float ex = dx-mu, ey = dy-mu, ez = dz-mu, ew = dw-mu;
    float ss = rsum16(ex*ex + ey*ey + ez*ez + ew*ew);
    float id = 1.f / (sqrtf(ss * (1.f/63.f)) + 1e-8f);    // ddof=1
    const float4 lw = *(const float4*)&tnw[h*64 + c4];
    const float4 lb = *(const float4*)&tnb[h*64 + c4];
    float4 nv;
    nv.x = lw.x*ex*id + lb.x + k.x;
    nv.y = lw.y*ey*id + lb.y + k.y;
    nv.z = lw.z*ez*id + lb.z + k.z;
    nv.w = lw.w*ew*id + lb.w + k.w;

    *(float4*)&g_q[base + r*64 + c4] = q;
    *(float4*)&g_k[base + r*64 + c4] = k;
    *(float4*)&g_v[base + r*64 + c4] = nv;

    *(float4*)&qs[r*64 + c4] = q;
    ksT[(c4+0)*17 + r] = k.x;
    ksT[(c4+1)*17 + r] = k.y;
    ksT[(c4+2)*17 + r] = k.z;
    ksT[(c4+3)*17 + r] = k.w;
    __syncthreads();

    // attn'[r][j] = (j<=r) ? (q[r].k[j] + 1) : 0
    float d = 0.f;
#pragma unroll 8
    for (int t2 = 0; t2 < 64; t2++) d += qs[r*64 + t2] * ksT[t2*17 + i2];
    g_attn[(size_t)t*256 + r*16 + i2] = (i2 <= r) ? (d + 1.f) : 0.f;
}

// ---------------------------------------------------------------------------
// Sequential TTT scan (R11 proven). One CTA per (b,h). 256 threads.
// ---------------------------------------------------------------------------
__global__ __launch_bounds__(256) void scan_kernel(
    const float* __restrict__ W1g, const float* __restrict__ b1g,
    const float* __restrict__ tnw, const float* __restrict__ tnb)
{
    __shared__ __align__(16) float W1s[64*64];
    __shared__ __align__(16) float xqs[1024];
    __shared__ __align__(16) float xks[1024];
    __shared__ __align__(16) float xvs[1024];
    __shared__ __align__(16) float grads[1024];
    __shared__ __align__(16) float xkTs[64*17];
    __shared__ __align__(16) float Ms[256];
    __shared__ float b1s[64], lnw[64], lnb[64], etas[16];

    const int bh = blockIdx.x;
    const int b = bh >> 5, h = bh & 31;
    const int tid = threadIdx.x;
    const int r = tid >> 4, i2 = tid & 15, c4 = i2*4;
    const int cu = tid & 63, qg = tid >> 6;         // update layout

    for (int i = tid; i < 4096; i += 256) W1s[i] = W1g[(size_t)h*4096 + i];
    if (tid < 64) {
        b1s[tid] = b1g[h*64 + tid];
        lnw[tid] = tnw[h*64 + tid];
        lnb[tid] = tnb[h*64 + tid];
    }

    const size_t tile0 = (size_t)bh * (NMBc * 1024);
    const size_t atn0  = (size_t)bh * (NMBc * 256);

    for (int j = 0; j < 4; j++) {
        int idx = tid + j*256;
        float vq = g_q[tile0+idx];
        float vk = g_k[tile0+idx];
        float vv = g_v[tile0+idx];
        xqs[idx] = vq; xks[idx] = vk; xvs[idx] = vv;
        xkTs[(idx & 63)*17 + (idx >> 6)] = vk;
    }
    Ms[tid] = g_attn[atn0 + tid];
    if (tid < 16) etas[tid] = g_eta[(size_t)bh*NMBc*Kc + tid];
    __syncthreads();

    for (int n = 0; n < NMBc; n++) {
        float rq[4], rk[4], rv[4], ra = 0.f, re = 0.f;
        const bool pf = (n + 1 < NMBc);
        if (pf) {
            const size_t tb = tile0 + (size_t)(n+1)*1024;
#pragma unroll
            for (int j = 0; j < 4; j++) {
                rq[j] = g_q[tb + tid + j*256];
                rk[j] = g_k[tb + tid + j*256];
                rv[j] = g_v[tb + tid + j*256];
            }
            ra = g_attn[atn0 + (size_t)(n+1)*256 + tid];
            if (tid < 16) re = g_eta[((size_t)bh*NMBc + n+1)*Kc + tid];
        }

        const float4 lw = *(const float4*)&lnw[c4];
        const float4 lb = *(const float4*)&lnb[c4];
        const float4 bb = *(const float4*)&b1s[c4];

        // ---- Phase A: Z1 -> LN stats -> grad (eta folded) ----
        {
            float4 z = bb;
#pragma unroll 8
            for (int k = 0; k < 64; k++) {
                float a = xks[r*64 + k];
                float4 w = *(const float4*)&W1s[k*64 + c4];
                z.x += a*w.x; z.y += a*w.y; z.z += a*w.z; z.w += a*w.w;
            }
            float mu = rsum16(z.x+z.y+z.z+z.w) * (1.f/64.f);
            float dx = z.x-mu, dy = z.y-mu, dz = z.z-mu, dw = z.w-mu;
            float var = rsum16(dx*dx+dy*dy+dz*dz+dw*dw) * (1.f/64.f);
            float stdv = sqrtf(var + 1e-6f);
            float inv = 1.f/stdv;
            float xhx = dx*inv, xhy = dy*inv, xhz = dz*inv, xhw = dw*inv;
            const float4 kv = *(const float4*)&xks[r*64 + c4];
            const float4 vv = *(const float4*)&xvs[r*64 + c4];
            float gx = (lw.x*xhx + lb.x - (vv.x - kv.x))*lw.x;
            float gy = (lw.y*xhy + lb.y - (vv.y - kv.y))*lw.y;
            float gz = (lw.z*xhz + lb.z - (vv.z - kv.z))*lw.z;
            float gw = (lw.w*xhw + lb.w - (vv.w - kv.w))*lw.w;
            float s1 = rsum16(gx+gy+gz+gw);
            float s2 = rsum16(gx*xhx + gy*xhy + gz*xhz + gw*xhw);
            float sc = etas[r] * (1.f/(64.f*stdv));
            float4 g4;
            g4.x = (64.f*gx - s1 - xhx*s2)*sc;
            g4.y = (64.f*gy - s1 - xhy*s2)*sc;
            g4.z = (64.f*gz - s1 - xhz*s2)*sc;
            g4.w = (64.f*gw - s1 - xhw*s2)*sc;
            *(float4*)&grads[r*64 + c4] = g4;
        }
        __syncthreads();

        // ---- Phase B: Z1_bar = xq@W1 + b1 - A'@eg -> LN -> output ----
        {
            float4 zb = bb;
#pragma unroll 8
            for (int k = 0; k < 64; k++) {
                float a = xqs[r*64 + k];
                float4 w = *(const float4*)&W1s[k*64 + c4];
                zb.x += a*w.x; zb.y += a*w.y; zb.z += a*w.z; zb.w += a*w.w;
            }
#pragma unroll
            for (int j = 0; j < 16; j++) {
                float m = Ms[r*16 + j];
                float4 g4 = *(const float4*)&grads[j*64 + c4];
                zb.x -= m*g4.x; zb.y -= m*g4.y; zb.z -= m*g4.z; zb.w -= m*g4.w;
            }
            float mu2 = rsum16(zb.x+zb.y+zb.z+zb.w) * (1.f/64.f);
            float ex = zb.x-mu2, ey = zb.y-mu2, ez = zb.z-mu2, ew = zb.w-mu2;
            float var2 = rsum16(ex*ex+ey*ey+ez*ez+ew*ew) * (1.f/64.f);
            float inv2 = rsqrtf(var2 + 1e-6f);
            const float4 q4 = *(const float4*)&xqs[r*64 + c4];
            float4 out;
            out.x = q4.x + ex*inv2*lw.x + lb.x;
            out.y = q4.y + ey*inv2*lw.y + lb.y;
            out.z = q4.z + ez*inv2*lw.z + lb.z;
            out.w = q4.w + ew*inv2*lw.w + lb.w;
            *(float4*)&g_y[((size_t)b*Lc + n*Kc + r)*Dc + h*HDc + c4] = out;
        }
        __syncthreads();

        // ---- Phase C: state update (W1 -= xkT@eg, b1 -= sum eg) ----
        {
            float greg[16];
#pragma unroll
            for (int j = 0; j < 16; j++) greg[j] = grads[j*64 + cu];
            if (qg == 0) {
                float s = 0.f;
#pragma unroll
                for (int j = 0; j < 16; j++) s += greg[j];
                b1s[cu] -= s;
            }
#pragma unroll
            for (int kk = 0; kk < 16; kk++) {
                int k = qg*16 + kk;
                float s = 0.f;
#pragma unroll
                for (int j = 0; j < 16; j++) s += xkTs[k*17 + j] * greg[j];
                W1s[k*64 + cu] -= s;
            }
        }
        __syncthreads();

        // ---- commit prefetched tile n+1 ----
        if (pf) {
#pragma unroll
            for (int j = 0; j < 4; j++) {
                int idx = tid + j*256;
                xqs[idx] = rq[j];
                xks[idx] = rk[j];
                xvs[idx] = rv[j];
                xkTs[(idx & 63)*17 + (idx >> 6)] = rk[j];
            }
            Ms[tid] = ra;
            if (tid < 16) etas[tid] = re;
        }
        __syncthreads();
    }
}

// ---------------------------------------------------------------------------
// Post layernorm over D=2048 per token; emits fp16 directly.
// ---------------------------------------------------------------------------
__global__ __launch_bounds__(256) void postnorm_kernel(
    const float* __restrict__ pw, const float* __restrict__ pb)
{
    __shared__ float red[8];
    __shared__ float smu, svar;
    const int row = blockIdx.x, tid = threadIdx.x;
    const int lane = tid & 31, wid = tid >> 5;
    const float* x = g_y + (size_t)row*Dc;

    float v[8];
    *(float4*)(v)   = *(const float4*)&x[tid*8];
    *(float4*)(v+4) = *(const float4*)&x[tid*8+4];

    float s = v[0]+v[1]+v[2]+v[3]+v[4]+v[5]+v[6]+v[7];
#pragma unroll
    for (int o = 16; o > 0; o >>= 1) s += __shfl_xor_sync(0xffffffffu, s, o);
    if (lane == 0) red[wid] = s;
    __syncthreads();
    if (tid == 0) {
        float t = 0.f;
#pragma unroll
        for (int i = 0; i < 8; i++) t += red[i];
        smu = t * (1.f/2048.f);
    }
    __syncthreads();
    float mu = smu;

    float ss = 0.f;
#pragma unroll
    for (int i = 0; i < 8; i++) { float d = v[i]-mu; ss += d*d; }
#pragma unroll
    for (int o = 16; o > 0; o >>= 1) ss += __shfl_xor_sync(0xffffffffu, ss, o);
    if (lane == 0) red[wid] = ss;
    __syncthreads();
    if (tid == 0) {
        float t = 0.f;
#pragma unroll
        for (int i = 0; i < 8; i++) t += red[i];
        svar = t * (1.f/2048.f);
    }
    __syncthreads();
    float rstd = rsqrtf(svar + 1e-6f);

    __half hb[8];
#pragma unroll
    for (int i = 0; i < 8; i++) {
        int cc = tid*8 + i;
        float y = (v[i]-mu)*rstd*pw[cc] + pb[cc];
        hb[i] = __float2half_rn(y);
    }
    *(uint4*)&g_xnh[(size_t)row*Dc + tid*8] = *(uint4*)hb;
}

// ---------------------------------------------------------------------------
extern "C" void kernel_launch(void* const* d_in, const int* in_sizes, int n_in,
                              void* d_out, int out_size)
{
    (void)in_sizes; (void)n_in; (void)out_size;
    const float* hs    = (const float*)d_in[0];
    const float* wq_w  = (const float*)d_in[1];
    const float* wq_b  = (const float*)d_in[2];
    const float* wk_w  = (const float*)d_in[3];
    const float* wk_b  = (const float*)d_in[4];
    const float* wv_w  = (const float*)d_in[5];
    const float* wv_b  = (const float*)d_in[6];
    const float* wo_w  = (const float*)d_in[7];
    const float* wo_b  = (const float*)d_in[8];
    const float* tnw   = (const float*)d_in[9];
    const float* tnb   = (const float*)d_in[10];
    const float* lr_w  = (const float*)d_in[11];
    const float* lr_b  = (const float*)d_in[12];
    const float* W1    = (const float*)d_in[13];
    const float* b1    = (const float*)d_in[14];
    const float* pnw   = (const float*)d_in[15];
    const float* pnb   = (const float*)d_in[16];

    __half* ah;
    cudaGetSymbolAddress((void**)&ah, g_ah);

    cudaFuncSetAttribute(hgemm_kernel,
                         cudaFuncAttributeMaxDynamicSharedMemorySize, HG_SMEM);

    const int nA = Mrows*Dc;     // 16.7M
    const int nW = Dc*Dc;        // 4.2M
    conv_hi_kernel<<<nA/1024, 256>>>(hs, ah, nA);
    conv4_kernel<<<dim3(nW/1024, 4), 256>>>(wq_w, wk_w, wv_w, wo_w);

    // merged QKV GEMM: grid.x = 3 matrices x 16 col-tiles (weights via symbols)
    hgemm_kernel<<<dim3(48, 64), 256, HG_SMEM>>>(wq_b, wk_b, wv_b, nullptr, 1);
    lr_gemm_kernel<<<Mrows/64, 256>>>(hs, lr_w, lr_b);
    preattn_kernel<<<Bb*Hh*NMBc, 256>>>(tnw, tnb);
    scan_kernel<<<Bb*Hh, 256>>>(W1, b1, tnw, tnb);
    postnorm_kernel<<<Mrows, 256>>>(pnw, pnb);
    hgemm_kernel<<<dim3(16, 64), 256, HG_SMEM>>>(wo_b, nullptr, nullptr,
                                                 (float*)d_out, 0);
}